// round 2
// baseline (speedup 1.0000x reference)
#include <cuda_runtime.h>
#include <cstdint>

// Int4Linear: y[m,n] = sum_k x[m,k] * W[n,k] + bias[n]
//   W[n,k] = (q[n,k] - zeros[n, k/64]) * scales[n, k/64]
//   q[n,2j]   = packed[n,j] & 15
//   q[n,2j+1] = (packed[n,j] >> 4) & 15
// Shapes (fixed): M = 2*2048 = 4096, K = 4096, N = 11008, G = 64.

#define M_DIM 4096
#define N_DIM 11008
#define K_DIM 4096
#define GRP   64
#define KT    16
#define BM    128
#define BN    128

// ---- packed fp32x2 helpers (Blackwell FFMA2 path; only reachable via PTX) ----
__device__ __forceinline__ unsigned long long pack2(float lo, float hi) {
    unsigned long long r;
    asm("mov.b64 %0, {%1, %2};" : "=l"(r) : "f"(lo), "f"(hi));
    return r;
}
__device__ __forceinline__ unsigned long long fma2(unsigned long long a,
                                                   unsigned long long b,
                                                   unsigned long long c) {
    unsigned long long d;
    asm("fma.rn.f32x2 %0, %1, %2, %3;" : "=l"(d) : "l"(a), "l"(b), "l"(c));
    return d;
}
__device__ __forceinline__ float2 unpack2(unsigned long long v) {
    float2 f;
    asm("mov.b64 {%0, %1}, %2;" : "=f"(f.x), "=f"(f.y) : "l"(v));
    return f;
}

__global__ __launch_bounds__(256, 2)
void int4linear_simt_kernel(const float* __restrict__ x,
                            const int*   __restrict__ packed,
                            const float* __restrict__ scales,
                            const int*   __restrict__ zeros,
                            const float* __restrict__ bias,
                            float*       __restrict__ out)
{
    __shared__ __align__(16) float As[KT][BM];   // As[k][m]
    __shared__ __align__(16) float Bs[KT][BN];   // Bs[k][n] (dequantized W)

    const int n0  = blockIdx.x * BN;
    const int m0  = blockIdx.y * BM;
    const int tid = threadIdx.x;
    const int tn  = tid & 15;    // 16 column groups of 8
    const int tm  = tid >> 4;    // 16 row groups of 8

    // 8 rows x 4 packed-pairs (= 8 cols) of f32x2 accumulators
    unsigned long long acc[8][4];
    #pragma unroll
    for (int i = 0; i < 8; i++)
        #pragma unroll
        for (int j = 0; j < 4; j++)
            acc[i][j] = 0ULL;

    // B-tile load mapping: 2 threads per output column, 4 packed int32 each
    const int bn_local = tid >> 1;   // 0..127 (column within tile)
    const int bhalf    = tid & 1;    // 0/1  (which 8 K-values)
    const int*   prow = packed + (size_t)(n0 + bn_local) * (K_DIM / 2);
    const float* srow = scales + (size_t)(n0 + bn_local) * (K_DIM / GRP);
    const int*   zrow = zeros  + (size_t)(n0 + bn_local) * (K_DIM / GRP);

    for (int k0 = 0; k0 < K_DIM; k0 += KT) {
        // ---- load A tile (128 rows x 16 k), store transposed ----
        #pragma unroll
        for (int i = 0; i < 2; i++) {
            int idx = tid * 2 + i;          // 0..511 float4 slots
            int row = idx >> 2;             // 0..127
            int c4  = idx & 3;              // 0..3 (float4 within the 16-k row)
            float4 v = *reinterpret_cast<const float4*>(
                &x[(size_t)(m0 + row) * K_DIM + k0 + c4 * 4]);
            As[c4 * 4 + 0][row] = v.x;
            As[c4 * 4 + 1][row] = v.y;
            As[c4 * 4 + 2][row] = v.z;
            As[c4 * 4 + 3][row] = v.w;
        }

        // ---- load + inline-dequant B tile (16 k x 128 n) ----
        {
            // group index is constant across a 16-wide K tile (64 % 16 == 0)
            const int   g  = k0 >> 6;
            const float s  = srow[g];
            const float zs = -(float)zrow[g] * s;   // W = q*s + zs
            int4 p = *reinterpret_cast<const int4*>(&prow[(k0 >> 1) + bhalf * 4]);
            const int kbase = bhalf * 8;
            int pv[4] = {p.x, p.y, p.z, p.w};
            #pragma unroll
            for (int c = 0; c < 4; c++) {
                Bs[kbase + c * 2 + 0][bn_local] = (float)( pv[c]       & 15) * s + zs;
                Bs[kbase + c * 2 + 1][bn_local] = (float)((pv[c] >> 4) & 15) * s + zs;
            }
        }
        __syncthreads();

        // ---- 8x8 micro-tile FMA, packed as f32x2 ----
        #pragma unroll
        for (int kk = 0; kk < KT; kk++) {
            float4 a0 = *reinterpret_cast<const float4*>(&As[kk][tm * 8]);
            float4 a1 = *reinterpret_cast<const float4*>(&As[kk][tm * 8 + 4]);
            float4 b0 = *reinterpret_cast<const float4*>(&Bs[kk][tn * 8]);
            float4 b1 = *reinterpret_cast<const float4*>(&Bs[kk][tn * 8 + 4]);
            unsigned long long bp[4] = {
                pack2(b0.x, b0.y), pack2(b0.z, b0.w),
                pack2(b1.x, b1.y), pack2(b1.z, b1.w)
            };
            // Pre-pack broadcast A operands once (keeps inner loop FFMA2-only)
            unsigned long long ap[8];
            ap[0] = pack2(a0.x, a0.x); ap[1] = pack2(a0.y, a0.y);
            ap[2] = pack2(a0.z, a0.z); ap[3] = pack2(a0.w, a0.w);
            ap[4] = pack2(a1.x, a1.x); ap[5] = pack2(a1.y, a1.y);
            ap[6] = pack2(a1.z, a1.z); ap[7] = pack2(a1.w, a1.w);
            #pragma unroll
            for (int i = 0; i < 8; i++) {
                #pragma unroll
                for (int j = 0; j < 4; j++)
                    acc[i][j] = fma2(ap[i], bp[j], acc[i][j]);
            }
        }
        __syncthreads();
    }

    // ---- epilogue: unpack, add bias, store ----
    #pragma unroll
    for (int i = 0; i < 8; i++) {
        const int m = m0 + tm * 8 + i;
        float* orow = out + (size_t)m * N_DIM + n0 + tn * 8;
        #pragma unroll
        for (int j = 0; j < 4; j++) {
            float2 v = unpack2(acc[i][j]);
            const int n = n0 + tn * 8 + j * 2;
            orow[j * 2 + 0] = v.x + bias[n];
            orow[j * 2 + 1] = v.y + bias[n + 1];
        }
    }
}

extern "C" void kernel_launch(void* const* d_in, const int* in_sizes, int n_in,
                              void* d_out, int out_size)
{
    const float* x      = (const float*)d_in[0];
    const int*   packed = (const int*)  d_in[1];
    const float* scales = (const float*)d_in[2];
    const int*   zeros  = (const int*)  d_in[3];
    const float* bias   = (const float*)d_in[4];
    float*       out    = (float*)d_out;

    dim3 grid(N_DIM / BN, M_DIM / BM);   // 86 x 32 blocks
    int4linear_simt_kernel<<<grid, 256>>>(x, packed, scales, zeros, bias, out);
}

// round 4
// speedup vs baseline: 4.0200x; 4.0200x over previous
#include <cuda_runtime.h>
#include <cstdint>

// Int4Linear via legacy tensor-core TF32 mma.sync (compute_100-safe; tcgen05
// is unavailable because the harness compiles through virtual arch compute_100).
//   y[m,n] = sum_k x[m,k] * W[n,k] + bias[n]
//   W[n,k] = (q - z) * s, q nibble-packed in int32.
// Shapes: M = 4096, K = 4096, N = 11008, group = 64.

#define M_DIM 4096
#define N_DIM 11008
#define K_DIM 4096
#define GRP   64

#define BM 128
#define BN 128
#define BK 32
#define PADF 4
#define LDSF (BK + PADF)          // 36 floats per smem row
#define TILEF (BM * LDSF)         // floats per (A or B) stage buffer
#define NITER (K_DIM / BK)        // 128

// 180 MB fp32 (tf32-rounded) dequantized weight scratch
__device__ float g_wdeq[(size_t)N_DIM * K_DIM];

__device__ __forceinline__ uint32_t smem_u32(const void* p) {
    uint32_t a;
    asm("{ .reg .u64 t; cvta.to.shared.u64 t, %1; cvt.u32.u64 %0, t; }"
        : "=r"(a) : "l"(p));
    return a;
}

#define CP_ASYNC16(dst, src) \
    asm volatile("cp.async.cg.shared.global [%0], [%1], 16;" \
                 :: "r"(dst), "l"(src) : "memory")
#define CP_COMMIT() asm volatile("cp.async.commit_group;" ::: "memory")

__device__ __forceinline__ float tf32_rna(float v) {
    uint32_t o;
    asm("cvt.rna.tf32.f32 %0, %1;" : "=r"(o) : "f"(v));
    return __uint_as_float(o);
}

__device__ __forceinline__ void mma_tf32(float* d, const uint32_t* a, const uint32_t* b) {
    asm volatile(
        "mma.sync.aligned.m16n8k8.row.col.f32.tf32.tf32.f32 "
        "{%0,%1,%2,%3}, {%4,%5,%6,%7}, {%8,%9}, {%0,%1,%2,%3};"
        : "+f"(d[0]), "+f"(d[1]), "+f"(d[2]), "+f"(d[3])
        : "r"(a[0]), "r"(a[1]), "r"(a[2]), "r"(a[3]), "r"(b[0]), "r"(b[1]));
}

// ---------------- kernel 1: dequant int4 -> fp32 (tf32-rounded) ----------------
__global__ __launch_bounds__(256)
void dequant_kernel(const int* __restrict__ packed,
                    const float* __restrict__ scales,
                    const int* __restrict__ zeros)
{
    int idx = blockIdx.x * 256 + threadIdx.x;      // over N_DIM * 1024
    int n  = idx >> 10;
    int j2 = idx & 1023;                           // one int2 -> 4 k-values
    int2 p = *reinterpret_cast<const int2*>(&packed[(size_t)n * (K_DIM / 2) + j2 * 2]);
    int g  = j2 >> 4;
    float s  = scales[(size_t)n * (K_DIM / GRP) + g];
    float zs = -(float)zeros[(size_t)n * (K_DIM / GRP) + g] * s;
    float4 v;
    v.x = tf32_rna((float)( p.x       & 15) * s + zs);
    v.y = tf32_rna((float)((p.x >> 4) & 15) * s + zs);
    v.z = tf32_rna((float)( p.y       & 15) * s + zs);
    v.w = tf32_rna((float)((p.y >> 4) & 15) * s + zs);
    *reinterpret_cast<float4*>(&g_wdeq[(size_t)n * K_DIM + j2 * 4]) = v;
}

// ---------------- kernel 2: tf32 mma.sync GEMM ----------------
#define SMEM_SZ (4 * TILEF * 4)   // 2 stages x (A+B) x TILEF floats x 4B = 73728

__global__ __launch_bounds__(256, 2)
void gemm_tf32_kernel(const float* __restrict__ x,
                      const float* __restrict__ bias,
                      float* __restrict__ out)
{
    extern __shared__ __align__(16) float smem[];
    float* As = smem;                 // [2][BM][LDSF]
    float* Bs = smem + 2 * TILEF;     // [2][BN][LDSF]

    const int tid    = threadIdx.x;
    const int lane   = tid & 31;
    const int wid    = tid >> 5;
    const int warp_m = wid & 1;       // 2 warps in m
    const int warp_n = wid >> 1;      // 4 warps in n
    const int m0 = blockIdx.x * BM;
    const int n0 = blockIdx.y * BN;

    const uint32_t as_u = smem_u32(As);
    const uint32_t bs_u = smem_u32(Bs);

    // global source rows for this thread's 4 cp.async slots (A and B identical mapping)
    const int ld_row = tid >> 3;          // +32 per i
    const int ld_c   = (tid & 7) * 4;     // float offset within BK row
    const float* a_src = x      + (size_t)(m0 + ld_row) * K_DIM + ld_c;
    const float* b_src = g_wdeq + (size_t)(n0 + ld_row) * K_DIM + ld_c;

    float acc[4][4][4];                   // [mtile][ntile][reg]
    #pragma unroll
    for (int i = 0; i < 4; i++)
        #pragma unroll
        for (int j = 0; j < 4; j++)
            #pragma unroll
            for (int r = 0; r < 4; r++)
                acc[i][j][r] = 0.0f;

    // ---- issue stage 0 ----
    {
        const uint32_t a_dst = as_u + (uint32_t)(ld_row * LDSF + ld_c) * 4;
        const uint32_t b_dst = bs_u + (uint32_t)(ld_row * LDSF + ld_c) * 4;
        #pragma unroll
        for (int i = 0; i < 4; i++) {
            CP_ASYNC16(a_dst + i * 32 * LDSF * 4, a_src + (size_t)i * 32 * K_DIM);
            CP_ASYNC16(b_dst + i * 32 * LDSF * 4, b_src + (size_t)i * 32 * K_DIM);
        }
        CP_COMMIT();
    }

    for (int it = 0; it < NITER; ++it) {
        const int buf = it & 1;

        // ---- issue stage it+1 into the other buffer ----
        if (it + 1 < NITER) {
            const int nb = (it + 1) & 1;
            const int k0 = (it + 1) * BK;
            const uint32_t a_dst = as_u + (uint32_t)(nb * TILEF + ld_row * LDSF + ld_c) * 4;
            const uint32_t b_dst = bs_u + (uint32_t)(nb * TILEF + ld_row * LDSF + ld_c) * 4;
            #pragma unroll
            for (int i = 0; i < 4; i++) {
                CP_ASYNC16(a_dst + i * 32 * LDSF * 4, a_src + (size_t)i * 32 * K_DIM + k0);
                CP_ASYNC16(b_dst + i * 32 * LDSF * 4, b_src + (size_t)i * 32 * K_DIM + k0);
            }
            CP_COMMIT();
            asm volatile("cp.async.wait_group 1;" ::: "memory");
        } else {
            asm volatile("cp.async.wait_group 0;" ::: "memory");
        }
        __syncthreads();

        // ---- compute on buf ----
        const float* aw = As + buf * TILEF + (warp_m * 64 + (lane >> 2)) * LDSF + (lane & 3);
        const float* bw = Bs + buf * TILEF + (warp_n * 32 + (lane >> 2)) * LDSF + (lane & 3);
        #pragma unroll
        for (int ks = 0; ks < BK / 8; ks++) {
            const int kk = ks * 8;
            uint32_t a[4][4], b[4][2];
            #pragma unroll
            for (int i = 0; i < 4; i++) {
                const float* p = aw + i * 16 * LDSF + kk;
                a[i][0] = __float_as_uint(p[0]);
                a[i][1] = __float_as_uint(p[8 * LDSF]);
                a[i][2] = __float_as_uint(p[4]);
                a[i][3] = __float_as_uint(p[8 * LDSF + 4]);
            }
            #pragma unroll
            for (int j = 0; j < 4; j++) {
                const float* p = bw + j * 8 * LDSF + kk;
                b[j][0] = __float_as_uint(p[0]);
                b[j][1] = __float_as_uint(p[4]);
            }
            #pragma unroll
            for (int i = 0; i < 4; i++)
                #pragma unroll
                for (int j = 0; j < 4; j++)
                    mma_tf32(acc[i][j], a[i], b[j]);
        }
        __syncthreads();   // all warps done with buf before it is refilled
    }

    // ---- epilogue: bias + store ----
    #pragma unroll
    for (int i = 0; i < 4; i++) {
        const int mrow = m0 + warp_m * 64 + i * 16 + (lane >> 2);
        #pragma unroll
        for (int j = 0; j < 4; j++) {
            const int n = n0 + warp_n * 32 + j * 8 + 2 * (lane & 3);
            const float b0 = bias[n], b1 = bias[n + 1];
            float2 v0 = make_float2(acc[i][j][0] + b0, acc[i][j][1] + b1);
            float2 v1 = make_float2(acc[i][j][2] + b0, acc[i][j][3] + b1);
            *reinterpret_cast<float2*>(out + (size_t)mrow * N_DIM + n) = v0;
            *reinterpret_cast<float2*>(out + (size_t)(mrow + 8) * N_DIM + n) = v1;
        }
    }
}

// ---------------- launch ----------------
extern "C" void kernel_launch(void* const* d_in, const int* in_sizes, int n_in,
                              void* d_out, int out_size)
{
    const float* x      = (const float*)d_in[0];
    const int*   packed = (const int*)  d_in[1];
    const float* scales = (const float*)d_in[2];
    const int*   zeros  = (const int*)  d_in[3];
    const float* bias   = (const float*)d_in[4];
    float*       out    = (float*)d_out;

    static int smem_set = 0;
    if (!smem_set) {
        cudaFuncSetAttribute(gemm_tf32_kernel,
                             cudaFuncAttributeMaxDynamicSharedMemorySize, SMEM_SZ);
        smem_set = 1;
    }

    dequant_kernel<<<(N_DIM * 1024) / 256, 256>>>(packed, scales, zeros);

    dim3 grid(M_DIM / BM, N_DIM / BN);   // m fastest -> A slice stays L2-resident
    gemm_tf32_kernel<<<grid, 256, SMEM_SZ>>>(x, bias, out);
}

// round 6
// speedup vs baseline: 8.6886x; 2.1613x over previous
#include <cuda_runtime.h>
#include <cuda_fp16.h>
#include <cstdint>

// Int4Linear via fp16 mma.sync.m16n8k16 (fp32 accum) + cp.async 4-stage pipeline.
//   y[m,n] = sum_k x[m,k] * W[n,k] + bias[n],  W = (q - z) * s  (int4 groupwise)
// Shapes: M = 4096, K = 4096, N = 11008, group = 64.
// fp16 storage of x and W keeps 11-bit mantissas (same as tf32) -> rel_err ~5e-4.

#define M_DIM 4096
#define N_DIM 11008
#define K_DIM 4096
#define GRP   64

#define BM 128
#define BN 128
#define BK 32
#define NITER (K_DIM / BK)        // 128
#define NSTAGE 4
#define SROWH 40                  // halves per smem row: 32 + 8 pad (80 B, conflict-free)
#define TILEH (128 * SROWH)       // halves per (A or B) stage tile
#define SMEM_SZ (NSTAGE * 2 * TILEH * 2)   // 81920 bytes

// fp16 scratch (allocation-guard-legal device globals)
__device__ __half g_wh[(size_t)N_DIM * K_DIM];   // 90 MB dequantized W
__device__ __half g_xh[(size_t)M_DIM * K_DIM];   // 32 MB x in fp16

__device__ __forceinline__ uint32_t smem_u32(const void* p) {
    uint32_t a;
    asm("{ .reg .u64 t; cvta.to.shared.u64 t, %1; cvt.u32.u64 %0, t; }"
        : "=r"(a) : "l"(p));
    return a;
}
#define CP_ASYNC16(dst, src) \
    asm volatile("cp.async.cg.shared.global [%0], [%1], 16;" \
                 :: "r"(dst), "l"(src) : "memory")
#define CP_COMMIT() asm volatile("cp.async.commit_group;" ::: "memory")

__device__ __forceinline__ void ldsm_x4(uint32_t* r, uint32_t addr) {
    asm volatile("ldmatrix.sync.aligned.m8n8.x4.shared.b16 {%0,%1,%2,%3}, [%4];"
                 : "=r"(r[0]), "=r"(r[1]), "=r"(r[2]), "=r"(r[3]) : "r"(addr));
}
__device__ __forceinline__ void mma_fp16(float* d, const uint32_t* a,
                                         uint32_t b0, uint32_t b1) {
    asm volatile(
        "mma.sync.aligned.m16n8k16.row.col.f32.f16.f16.f32 "
        "{%0,%1,%2,%3}, {%4,%5,%6,%7}, {%8,%9}, {%0,%1,%2,%3};"
        : "+f"(d[0]), "+f"(d[1]), "+f"(d[2]), "+f"(d[3])
        : "r"(a[0]), "r"(a[1]), "r"(a[2]), "r"(a[3]), "r"(b0), "r"(b1));
}

// -------- prepass 1: x fp32 -> fp16 --------
__global__ __launch_bounds__(256)
void convert_x_kernel(const float* __restrict__ x)
{
    size_t idx = (size_t)blockIdx.x * 256 + threadIdx.x;   // over M*K/8
    const float4 v0 = *reinterpret_cast<const float4*>(x + idx * 8);
    const float4 v1 = *reinterpret_cast<const float4*>(x + idx * 8 + 4);
    __half2 h[4];
    h[0] = __floats2half2_rn(v0.x, v0.y);
    h[1] = __floats2half2_rn(v0.z, v0.w);
    h[2] = __floats2half2_rn(v1.x, v1.y);
    h[3] = __floats2half2_rn(v1.z, v1.w);
    *reinterpret_cast<uint4*>(&g_xh[idx * 8]) = *reinterpret_cast<uint4*>(h);
}

// -------- prepass 2: int4 dequant -> fp16 --------
__global__ __launch_bounds__(256)
void dequant_kernel(const int* __restrict__ packed,
                    const float* __restrict__ scales,
                    const int* __restrict__ zeros)
{
    size_t idx = (size_t)blockIdx.x * 256 + threadIdx.x;   // over N*K/8
    int n  = (int)(idx >> 9);                              // 512 int4-slots per row
    int j4 = (int)(idx & 511);                             // 4 int32 -> 8 k-values
    int4 p = *reinterpret_cast<const int4*>(&packed[(size_t)n * (K_DIM / 2) + j4 * 4]);
    int g  = j4 >> 3;                                      // (j4*8)/64
    float s  = scales[(size_t)n * (K_DIM / GRP) + g];
    float zs = -(float)zeros[(size_t)n * (K_DIM / GRP) + g] * s;
    int pv[4] = {p.x, p.y, p.z, p.w};
    __half2 h[4];
    #pragma unroll
    for (int c = 0; c < 4; c++)
        h[c] = __floats2half2_rn((float)( pv[c]       & 15) * s + zs,
                                 (float)((pv[c] >> 4) & 15) * s + zs);
    *reinterpret_cast<uint4*>(&g_wh[(size_t)n * K_DIM + j4 * 8]) = *reinterpret_cast<uint4*>(h);
}

// -------- GEMM: fp16 mma.sync, 4-stage cp.async pipeline --------
__global__ __launch_bounds__(256, 2)
void gemm_fp16_kernel(const float* __restrict__ bias,
                      float* __restrict__ out)
{
    extern __shared__ __align__(16) __half smem[];
    __half* As = smem;                       // [NSTAGE][128][SROWH]
    __half* Bs = smem + NSTAGE * TILEH;

    const int tid    = threadIdx.x;
    const int lane   = tid & 31;
    const int wid    = tid >> 5;
    const int warp_m = wid & 1;              // 2 warps in m -> 64 rows each
    const int warp_n = wid >> 1;             // 4 warps in n -> 32 cols each
    const int m0 = blockIdx.x * BM;
    const int n0 = blockIdx.y * BN;

    const uint32_t as_u = smem_u32(As);
    const uint32_t bs_u = smem_u32(Bs);

    // cp.async mapping: 512 16B-chunks per tile, 2 per thread per tile
    const int ld_row = tid >> 2;             // 0..63, +64 for second chunk
    const int ld_c16 = tid & 3;              // 16B column within 64B row
    const __half* a_src = g_xh + (size_t)(m0 + ld_row) * K_DIM + ld_c16 * 8;
    const __half* b_src = g_wh + (size_t)(n0 + ld_row) * K_DIM + ld_c16 * 8;
    const uint32_t a_dst0 = as_u + (uint32_t)(ld_row * SROWH) * 2 + ld_c16 * 16;
    const uint32_t b_dst0 = bs_u + (uint32_t)(ld_row * SROWH) * 2 + ld_c16 * 16;

    float acc[4][4][4];
    #pragma unroll
    for (int i = 0; i < 4; i++)
        #pragma unroll
        for (int j = 0; j < 4; j++)
            #pragma unroll
            for (int r = 0; r < 4; r++) acc[i][j][r] = 0.0f;

    // prologue: stages 0..NSTAGE-2
    #pragma unroll
    for (int s = 0; s < NSTAGE - 1; s++) {
        const int k0 = s * BK;
        #pragma unroll
        for (int h = 0; h < 2; h++) {
            CP_ASYNC16(a_dst0 + (uint32_t)(s * TILEH + h * 64 * SROWH) * 2,
                       a_src + (size_t)h * 64 * K_DIM + k0);
            CP_ASYNC16(b_dst0 + (uint32_t)(s * TILEH + h * 64 * SROWH) * 2,
                       b_src + (size_t)h * 64 * K_DIM + k0);
        }
        CP_COMMIT();
    }

    // per-warp ldmatrix base addresses (lane-dependent)
    // A x4: rows m + (lane&15), k halves split by (lane>>4)*8
    const uint32_t a_frag0 = as_u +
        (uint32_t)((warp_m * 64 + (lane & 15)) * SROWH + (lane >> 4) * 8) * 2;
    // B x4: rows n + (lane>>4)*8 + (lane&7), k split by ((lane>>3)&1)*8
    const uint32_t b_frag0 = bs_u +
        (uint32_t)((warp_n * 32 + ((lane >> 4) * 8) + (lane & 7)) * SROWH +
                   (((lane >> 3) & 1) * 8)) * 2;

    for (int it = 0; it < NITER; ++it) {
        asm volatile("cp.async.wait_group %0;" :: "n"(NSTAGE - 2) : "memory");
        __syncthreads();

        const uint32_t soff = (uint32_t)((it & (NSTAGE - 1)) * TILEH) * 2;

        #pragma unroll
        for (int ks = 0; ks < BK / 16; ks++) {
            uint32_t a[4][4], b[2][4];
            #pragma unroll
            for (int i = 0; i < 4; i++)
                ldsm_x4(a[i], a_frag0 + soff + (uint32_t)(i * 16 * SROWH + ks * 16) * 2);
            #pragma unroll
            for (int j2 = 0; j2 < 2; j2++)
                ldsm_x4(b[j2], b_frag0 + soff + (uint32_t)(j2 * 16 * SROWH + ks * 16) * 2);
            #pragma unroll
            for (int i = 0; i < 4; i++)
                #pragma unroll
                for (int j = 0; j < 4; j++)
                    mma_fp16(acc[i][j], a[i], b[j >> 1][(j & 1) * 2],
                             b[j >> 1][(j & 1) * 2 + 1]);
        }

        // prefetch stage it+NSTAGE-1 into buffer (it-1)%NSTAGE (safe: consumed
        // last iter, and all warps passed this iter's syncthreads)
        const int pf = it + NSTAGE - 1;
        if (pf < NITER) {
            const int k0 = pf * BK;
            const uint32_t poff = (uint32_t)((pf & (NSTAGE - 1)) * TILEH) * 2;
            #pragma unroll
            for (int h = 0; h < 2; h++) {
                CP_ASYNC16(a_dst0 + poff + (uint32_t)(h * 64 * SROWH) * 2,
                           a_src + (size_t)h * 64 * K_DIM + k0);
                CP_ASYNC16(b_dst0 + poff + (uint32_t)(h * 64 * SROWH) * 2,
                           b_src + (size_t)h * 64 * K_DIM + k0);
            }
        }
        CP_COMMIT();   // commit every iter (possibly empty) to keep group counts aligned
    }

    // -------- epilogue: bias + store --------
    #pragma unroll
    for (int i = 0; i < 4; i++) {
        const int mrow = m0 + warp_m * 64 + i * 16 + (lane >> 2);
        #pragma unroll
        for (int j = 0; j < 4; j++) {
            const int n = n0 + warp_n * 32 + j * 8 + 2 * (lane & 3);
            const float b0 = bias[n], b1 = bias[n + 1];
            float2 v0 = make_float2(acc[i][j][0] + b0, acc[i][j][1] + b1);
            float2 v1 = make_float2(acc[i][j][2] + b0, acc[i][j][3] + b1);
            *reinterpret_cast<float2*>(out + (size_t)mrow * N_DIM + n) = v0;
            *reinterpret_cast<float2*>(out + (size_t)(mrow + 8) * N_DIM + n) = v1;
        }
    }
}

// -------- launch --------
extern "C" void kernel_launch(void* const* d_in, const int* in_sizes, int n_in,
                              void* d_out, int out_size)
{
    const float* x      = (const float*)d_in[0];
    const int*   packed = (const int*)  d_in[1];
    const float* scales = (const float*)d_in[2];
    const int*   zeros  = (const int*)  d_in[3];
    const float* bias   = (const float*)d_in[4];
    float*       out    = (float*)d_out;

    static int smem_set = 0;
    if (!smem_set) {
        cudaFuncSetAttribute(gemm_fp16_kernel,
                             cudaFuncAttributeMaxDynamicSharedMemorySize, SMEM_SZ);
        smem_set = 1;
    }

    convert_x_kernel<<<(int)(((size_t)M_DIM * K_DIM / 8) / 256), 256>>>(x);
    dequant_kernel<<<(int)(((size_t)N_DIM * K_DIM / 8) / 256), 256>>>(packed, scales, zeros);

    dim3 grid(M_DIM / BM, N_DIM / BN);   // m fastest -> strong L2 reuse
    gemm_fp16_kernel<<<grid, 256, SMEM_SZ>>>(bias, out);
}